// round 1
// baseline (speedup 1.0000x reference)
#include <cuda_runtime.h>
#include <cstdint>
#include <cstddef>

// ---------------------------------------------------------------------------
// Problem constants
// ---------------------------------------------------------------------------
#define B_SZ   32
#define NTOK   577
#define HEADS  8
#define DIM_C  512
#define HD     64
#define MROWS  (B_SZ * NTOK)          // 18464
#define NN     (NTOK * NTOK)          // 332929
#define QKVW   (3 * DIM_C)            // 1536

// ---------------------------------------------------------------------------
// Scratch (static __device__ arrays; runtime allocation is forbidden)
// ---------------------------------------------------------------------------
__device__ float g_qkv[MROWS * QKVW];     // [B*N, 1536]  (q|k|v, head-major inside each 512)
__device__ float g_bias[HEADS * NN];      // [H, N, N]
__device__ float g_att[MROWS * DIM_C];    // attention output, [B*N, 512]

// ---------------------------------------------------------------------------
// Kernel 0: materialize relative-position bias  bias[h][i][j]
// ---------------------------------------------------------------------------
__global__ void __launch_bounds__(256) bias_kernel(const float* __restrict__ table,
                                                   const int* __restrict__ rel) {
    int ij = blockIdx.x * 256 + threadIdx.x;
    if (ij >= NN) return;
    int idx = rel[ij];
    const float* t = table + (size_t)idx * HEADS;
#pragma unroll
    for (int h = 0; h < HEADS; h++)
        g_bias[(size_t)h * NN + ij] = t[h];
}

// ---------------------------------------------------------------------------
// Tiled SGEMM:  C[M,N] = A[M,K] @ B[N,K]^T  (+ bias[N])
// 128x128 tile, BK=16, 256 threads, 8x8 microtile.
// N and K must be multiples of 128 / 16 (true here: 1536/512, 512).
// ---------------------------------------------------------------------------
template<bool ADD_BIAS>
__global__ void __launch_bounds__(256) gemm_tn(const float* __restrict__ A,
                                               const float* __restrict__ Bm,
                                               const float* __restrict__ bias,
                                               float* __restrict__ C,
                                               int M, int N, int K) {
    __shared__ float As[16][132];   // [k][row], padded
    __shared__ float Bs[16][132];   // [k][col], padded

    const int tid  = threadIdx.x;
    const int tx   = tid & 15;
    const int ty   = tid >> 4;
    const int lrow = tid >> 2;          // 0..63
    const int lk   = (tid & 3) * 4;     // 0,4,8,12

    const int row0 = blockIdx.y * 128;
    const int col0 = blockIdx.x * 128;

    float acc[8][8];
#pragma unroll
    for (int i = 0; i < 8; i++)
#pragma unroll
        for (int j = 0; j < 8; j++) acc[i][j] = 0.f;

    for (int k0 = 0; k0 < K; k0 += 16) {
        // ---- load A tile (two 64-row halves) ----
#pragma unroll
        for (int half = 0; half < 2; half++) {
            int r  = lrow + half * 64;
            int ar = row0 + r;
            float4 av = make_float4(0.f, 0.f, 0.f, 0.f);
            if (ar < M)
                av = *reinterpret_cast<const float4*>(A + (size_t)ar * K + k0 + lk);
            As[lk + 0][r] = av.x; As[lk + 1][r] = av.y;
            As[lk + 2][r] = av.z; As[lk + 3][r] = av.w;

            int bc = col0 + r;   // always < N (N multiple of 128)
            float4 bv = *reinterpret_cast<const float4*>(Bm + (size_t)bc * K + k0 + lk);
            Bs[lk + 0][r] = bv.x; Bs[lk + 1][r] = bv.y;
            Bs[lk + 2][r] = bv.z; Bs[lk + 3][r] = bv.w;
        }
        __syncthreads();

#pragma unroll
        for (int k = 0; k < 16; k++) {
            float a[8], b[8];
#pragma unroll
            for (int i = 0; i < 8; i++) a[i] = As[k][ty * 8 + i];
#pragma unroll
            for (int j = 0; j < 8; j++) b[j] = Bs[k][tx * 8 + j];
#pragma unroll
            for (int i = 0; i < 8; i++)
#pragma unroll
                for (int j = 0; j < 8; j++)
                    acc[i][j] = fmaf(a[i], b[j], acc[i][j]);
        }
        __syncthreads();
    }

    // ---- epilogue ----
#pragma unroll
    for (int i = 0; i < 8; i++) {
        int r = row0 + ty * 8 + i;
        if (r >= M) continue;
        float* crow = C + (size_t)r * N + col0 + tx * 8;
#pragma unroll
        for (int j4 = 0; j4 < 2; j4++) {
            float4 v;
            int j = j4 * 4;
            v.x = acc[i][j + 0]; v.y = acc[i][j + 1];
            v.z = acc[i][j + 2]; v.w = acc[i][j + 3];
            if (ADD_BIAS) {
                const float* bp = bias + col0 + tx * 8 + j;
                v.x += bp[0]; v.y += bp[1]; v.z += bp[2]; v.w += bp[3];
            }
            *reinterpret_cast<float4*>(crow + j) = v;
        }
    }
}

// ---------------------------------------------------------------------------
// Flash-style attention.
// grid = (10 row-tiles, HEADS, B). 256 threads, 4x4 microtile per thread.
// smem: Qs[k][r], Ks[k][c], Vs[m][d], Ps[c][r]  each 64x68 fp32.
// ---------------------------------------------------------------------------
#define SMW 68
#define ATTN_SMEM_BYTES (4 * 64 * SMW * 4)   // 69632

__global__ void __launch_bounds__(256) attn_kernel() {
    extern __shared__ float sm[];
    float* Qs = sm;                 // Qs[k*SMW + r]
    float* Ks = Qs + 64 * SMW;      // Ks[k*SMW + c]
    float* Vs = Ks + 64 * SMW;      // Vs[m*SMW + d]
    float* Ps = Vs + 64 * SMW;      // Ps[c*SMW + r]

    const int tid = threadIdx.x;
    const int tx  = tid & 15;
    const int ty  = tid >> 4;
    const int r_l = ty * 4;
    const int c_l = tx * 4;

    const int b    = blockIdx.z;
    const int h    = blockIdx.y;
    const int row0 = blockIdx.x * 64;

    const float* base = g_qkv + (size_t)b * NTOK * QKVW + h * HD;
    const float* qb = base;
    const float* kb = base + DIM_C;
    const float* vb = base + 2 * DIM_C;
    const float* bb = g_bias + (size_t)h * NN;

    // ---- load Q tile (transposed: Qs[k][r]) ----
    for (int idx = tid; idx < 64 * 64; idx += 256) {
        int r = idx >> 6, k = idx & 63;
        int gr = row0 + r;
        Qs[k * SMW + r] = (gr < NTOK) ? qb[(size_t)gr * QKVW + k] : 0.f;
    }

    float mprev[4], lsum[4], acc[4][4];
#pragma unroll
    for (int i = 0; i < 4; i++) {
        mprev[i] = -1e30f; lsum[i] = 0.f;
#pragma unroll
        for (int j = 0; j < 4; j++) acc[i][j] = 0.f;
    }

    const float scale = 0.125f;   // 64^-0.5

    for (int jt = 0; jt < 10; jt++) {
        const int col0 = jt * 64;
        __syncthreads();
        // ---- load K (transposed) and V tiles ----
        for (int idx = tid; idx < 64 * 64; idx += 256) {
            int c = idx >> 6, k = idx & 63;
            int gc = col0 + c;
            float kk = 0.f, vv = 0.f;
            if (gc < NTOK) {
                kk = kb[(size_t)gc * QKVW + k];
                vv = vb[(size_t)gc * QKVW + k];
            }
            Ks[k * SMW + c] = kk;
            Vs[c * SMW + k] = vv;
        }
        __syncthreads();

        // ---- S = Q K^T ----
        float s[4][4];
#pragma unroll
        for (int i = 0; i < 4; i++)
#pragma unroll
            for (int j = 0; j < 4; j++) s[i][j] = 0.f;

#pragma unroll 16
        for (int k = 0; k < 64; k++) {
            float qa[4], kf[4];
#pragma unroll
            for (int i = 0; i < 4; i++) qa[i] = Qs[k * SMW + r_l + i];
#pragma unroll
            for (int j = 0; j < 4; j++) kf[j] = Ks[k * SMW + c_l + j];
#pragma unroll
            for (int i = 0; i < 4; i++)
#pragma unroll
                for (int j = 0; j < 4; j++)
                    s[i][j] = fmaf(qa[i], kf[j], s[i][j]);
        }

        // ---- scale + bias + column mask ----
#pragma unroll
        for (int i = 0; i < 4; i++) {
            int gr = row0 + r_l + i;
            int gr_c = gr < NTOK ? gr : (NTOK - 1);       // clamp, row discarded anyway
            const float* brow = bb + (size_t)gr_c * NTOK;
#pragma unroll
            for (int j = 0; j < 4; j++) {
                int gc = col0 + c_l + j;
                s[i][j] = (gc < NTOK) ? (s[i][j] * scale + brow[gc]) : -1e30f;
            }
        }

        // ---- online softmax (reduce over 16 lanes sharing a row group) ----
#pragma unroll
        for (int i = 0; i < 4; i++) {
            float mx = fmaxf(fmaxf(s[i][0], s[i][1]), fmaxf(s[i][2], s[i][3]));
#pragma unroll
            for (int off = 1; off < 16; off <<= 1)
                mx = fmaxf(mx, __shfl_xor_sync(0xffffffffu, mx, off));
            float mnew  = fmaxf(mprev[i], mx);
            float alpha = __expf(mprev[i] - mnew);
            float rs = 0.f;
#pragma unroll
            for (int j = 0; j < 4; j++) {
                float p = __expf(s[i][j] - mnew);
                s[i][j] = p;
                rs += p;
            }
#pragma unroll
            for (int off = 1; off < 16; off <<= 1)
                rs += __shfl_xor_sync(0xffffffffu, rs, off);
            lsum[i]  = lsum[i] * alpha + rs;
            mprev[i] = mnew;
#pragma unroll
            for (int j = 0; j < 4; j++) acc[i][j] *= alpha;
            // store P transposed: Ps[c][r]
#pragma unroll
            for (int j = 0; j < 4; j++)
                Ps[(c_l + j) * SMW + (r_l + i)] = s[i][j];
        }
        __syncthreads();

        // ---- acc += P @ V ----
#pragma unroll 8
        for (int m = 0; m < 64; m++) {
            float pa[4], vf[4];
#pragma unroll
            for (int i = 0; i < 4; i++) pa[i] = Ps[m * SMW + r_l + i];
#pragma unroll
            for (int j = 0; j < 4; j++) vf[j] = Vs[m * SMW + c_l + j];
#pragma unroll
            for (int i = 0; i < 4; i++)
#pragma unroll
                for (int j = 0; j < 4; j++)
                    acc[i][j] = fmaf(pa[i], vf[j], acc[i][j]);
        }
    }

    // ---- epilogue: normalize & write [B,N, h*64 + d] ----
#pragma unroll
    for (int i = 0; i < 4; i++) {
        int gr = row0 + r_l + i;
        if (gr >= NTOK) continue;
        float inv = 1.0f / lsum[i];
        float4 v;
        v.x = acc[i][0] * inv; v.y = acc[i][1] * inv;
        v.z = acc[i][2] * inv; v.w = acc[i][3] * inv;
        *reinterpret_cast<float4*>(
            g_att + ((size_t)b * NTOK + gr) * DIM_C + h * HD + c_l) = v;
    }
}

// ---------------------------------------------------------------------------
// Launcher
// ---------------------------------------------------------------------------
extern "C" void kernel_launch(void* const* d_in, const int* in_sizes, int n_in,
                              void* d_out, int out_size) {
    const float* x      = (const float*)d_in[0];
    const float* qkv_w  = (const float*)d_in[1];
    const float* proj_w = (const float*)d_in[2];
    const float* proj_b = (const float*)d_in[3];
    const float* table  = (const float*)d_in[4];
    const int*   rel    = (const int*)d_in[5];
    float*       out    = (float*)d_out;

    void *qkv_p = nullptr, *att_p = nullptr;
    cudaGetSymbolAddress(&qkv_p, g_qkv);
    cudaGetSymbolAddress(&att_p, g_att);

    cudaFuncSetAttribute(attn_kernel,
                         cudaFuncAttributeMaxDynamicSharedMemorySize,
                         ATTN_SMEM_BYTES);

    // 1) bias materialization (independent of x)
    bias_kernel<<<(NN + 255) / 256, 256>>>(table, rel);

    // 2) QKV projection: [18464,512] x [1536,512]^T -> [18464,1536]
    gemm_tn<false><<<dim3(QKVW / 128, (MROWS + 127) / 128), 256>>>(
        x, qkv_w, nullptr, (float*)qkv_p, MROWS, QKVW, DIM_C);

    // 3) attention
    attn_kernel<<<dim3(10, HEADS, B_SZ), 256, ATTN_SMEM_BYTES>>>();

    // 4) output projection + bias -> d_out
    gemm_tn<true><<<dim3(DIM_C / 128, (MROWS + 127) / 128), 256>>>(
        (const float*)att_p, proj_w, proj_b, out, MROWS, DIM_C, DIM_C);
}

// round 3
// speedup vs baseline: 1.5871x; 1.5871x over previous
#include <cuda_runtime.h>
#include <cstdint>
#include <cstddef>

// ---------------------------------------------------------------------------
// Problem constants
// ---------------------------------------------------------------------------
#define B_SZ   32
#define NTOK   577
#define HEADS  8
#define DIM_C  512
#define HD     64
#define MROWS  (B_SZ * NTOK)          // 18464
#define NN     (NTOK * NTOK)          // 332929
#define QKVW   (3 * DIM_C)            // 1536

// ---------------------------------------------------------------------------
// Scratch
// ---------------------------------------------------------------------------
__device__ float g_qkv[MROWS * QKVW];     // [B*N, 1536]
__device__ float g_bias[HEADS * NN];      // [H, N, N]
__device__ float g_att[MROWS * DIM_C];    // [B*N, 512]

// ---------------------------------------------------------------------------
// tf32 helpers
// ---------------------------------------------------------------------------
__device__ __forceinline__ unsigned f2tf32(float x) {
    unsigned r;
    asm("cvt.rna.tf32.f32 %0, %1;" : "=r"(r) : "f"(x));
    return r;
}

__device__ __forceinline__ void mma_tf32(float* d, const uint4& a, const uint2& b) {
    asm volatile(
        "mma.sync.aligned.m16n8k8.row.col.f32.tf32.tf32.f32 "
        "{%0,%1,%2,%3}, {%4,%5,%6,%7}, {%8,%9}, {%0,%1,%2,%3};\n"
        : "+f"(d[0]), "+f"(d[1]), "+f"(d[2]), "+f"(d[3])
        : "r"(a.x), "r"(a.y), "r"(a.z), "r"(a.w), "r"(b.x), "r"(b.y));
}

// ---------------------------------------------------------------------------
// Kernel 0: materialize relative-position bias  bias[h][i][j]
// ---------------------------------------------------------------------------
__global__ void __launch_bounds__(256) bias_kernel(const float* __restrict__ table,
                                                   const int* __restrict__ rel) {
    int ij = blockIdx.x * 256 + threadIdx.x;
    if (ij >= NN) return;
    int idx = rel[ij];
    const float* t = table + (size_t)idx * HEADS;
#pragma unroll
    for (int h = 0; h < HEADS; h++)
        g_bias[(size_t)h * NN + ij] = t[h];
}

// ---------------------------------------------------------------------------
// tf32 tensor-core GEMM:  C[M,N] = A[M,K] @ B[N,K]^T (+ bias[N])
// 128x128 block tile, BK=32, 256 threads = 8 warps (2M x 4N), warp 64x32.
// Smem tiles stored in mma fragment order: A-frag = 1 LDS.128, B-frag = 1 LDS.64.
// ---------------------------------------------------------------------------
template<bool ADD_BIAS>
__global__ void __launch_bounds__(256) gemm_tf32(const float* __restrict__ A,
                                                 const float* __restrict__ Bm,
                                                 const float* __restrict__ bias,
                                                 float* __restrict__ C,
                                                 int M, int N, int K) {
    __shared__ unsigned Asm[4096];   // [ks(4)][mt(8)] subtiles of 128
    __shared__ unsigned Bsm[4096];   // [ks(4)][nt(16)] subtiles of 64

    const int tid  = threadIdx.x;
    const int lane = tid & 31;
    const int w    = tid >> 5;
    const int wm   = w >> 2;          // 0..1
    const int wn   = w & 3;           // 0..3

    const int row0 = blockIdx.y * 128;
    const int col0 = blockIdx.x * 128;

    float acc[4][4][4];
#pragma unroll
    for (int i = 0; i < 4; i++)
#pragma unroll
        for (int j = 0; j < 4; j++)
#pragma unroll
            for (int r = 0; r < 4; r++) acc[i][j][r] = 0.f;

    for (int k0 = 0; k0 < K; k0 += 32) {
        // ---- fill A tile in A-fragment order ----
#pragma unroll
        for (int l = 0; l < 4; l++) {
            int linear = tid + l * 256;             // 0..1023
            int row = linear >> 3;                  // 0..127
            int k4  = (linear & 7) * 4;
            int gr  = row0 + row;
            float4 v = make_float4(0.f, 0.f, 0.f, 0.f);
            if (gr < M)
                v = *reinterpret_cast<const float4*>(A + (size_t)gr * K + k0 + k4);
            int mt = row >> 4, rr = row & 15;
            const float vv[4] = {v.x, v.y, v.z, v.w};
#pragma unroll
            for (int c = 0; c < 4; c++) {
                int k  = k4 + c;
                int ks = k >> 3, kc = k & 7;
                int ln = (rr & 7) * 4 + (kc & 3);
                int rg = (rr >> 3) + ((kc >> 2) << 1);
                Asm[(ks * 8 + mt) * 128 + ln * 4 + rg] = f2tf32(vv[c]);
            }
        }
        // ---- fill B tile in B-fragment order ----
#pragma unroll
        for (int l = 0; l < 4; l++) {
            int linear = tid + l * 256;
            int n  = linear >> 3;                   // 0..127
            int k4 = (linear & 7) * 4;
            int gn = col0 + n;                      // always < N
            float4 v = *reinterpret_cast<const float4*>(Bm + (size_t)gn * K + k0 + k4);
            int nt = n >> 3, nn = n & 7;
            const float vv[4] = {v.x, v.y, v.z, v.w};
#pragma unroll
            for (int c = 0; c < 4; c++) {
                int k  = k4 + c;
                int ks = k >> 3, kc = k & 7;
                int ln = nn * 4 + (kc & 3);
                int rg = kc >> 2;
                Bsm[(ks * 16 + nt) * 64 + ln * 2 + rg] = f2tf32(vv[c]);
            }
        }
        __syncthreads();

#pragma unroll
        for (int ks = 0; ks < 4; ks++) {
            uint4 a[4];
            uint2 b[4];
#pragma unroll
            for (int i = 0; i < 4; i++)
                a[i] = *reinterpret_cast<const uint4*>(
                    &Asm[(ks * 8 + wm * 4 + i) * 128 + lane * 4]);
#pragma unroll
            for (int j = 0; j < 4; j++)
                b[j] = *reinterpret_cast<const uint2*>(
                    &Bsm[(ks * 16 + wn * 4 + j) * 64 + lane * 2]);
#pragma unroll
            for (int i = 0; i < 4; i++)
#pragma unroll
                for (int j = 0; j < 4; j++)
                    mma_tf32(acc[i][j], a[i], b[j]);
        }
        __syncthreads();
    }

    // ---- epilogue ----
    const int g = lane >> 2, t = lane & 3;
#pragma unroll
    for (int i = 0; i < 4; i++) {
        int r_up = row0 + wm * 64 + i * 16 + g;
        int r_lo = r_up + 8;
#pragma unroll
        for (int j = 0; j < 4; j++) {
            int c = col0 + wn * 32 + j * 8 + t * 2;
            float bx = 0.f, by = 0.f;
            if (ADD_BIAS) { bx = bias[c]; by = bias[c + 1]; }
            if (r_up < M) {
                float2 v = make_float2(acc[i][j][0] + bx, acc[i][j][1] + by);
                *reinterpret_cast<float2*>(C + (size_t)r_up * N + c) = v;
            }
            if (r_lo < M) {
                float2 v = make_float2(acc[i][j][2] + bx, acc[i][j][3] + by);
                *reinterpret_cast<float2*>(C + (size_t)r_lo * N + c) = v;
            }
        }
    }
}

// ---------------------------------------------------------------------------
// Flash attention with tf32 mma.
// grid = (10, HEADS, B), 128 threads = 4 warps; warp owns 16 query rows.
// Smem (dynamic 64KB): Qf / Kf / Vf / Pf, all in fragment order.
// ---------------------------------------------------------------------------
#define ATTN_SMEM_BYTES 65536

__global__ void __launch_bounds__(128) attn_mma_kernel() {
    extern __shared__ unsigned smu[];
    unsigned* Qf = smu;            // A-frag: [(mt*8+ks)*128 + lane*4 + reg]
    unsigned* Kf = smu + 4096;     // B-frag: [(ks*8+nt)*64 + lane*2 + reg]
    unsigned* Vf = smu + 8192;     // B-frag
    unsigned* Pf = smu + 12288;    // A-frag (warp-private mt = warp)

    const int tid  = threadIdx.x;
    const int lane = tid & 31;
    const int w    = tid >> 5;
    const int g    = lane >> 2;
    const int t    = lane & 3;

    const int b    = blockIdx.z;
    const int h    = blockIdx.y;
    const int row0 = blockIdx.x * 64;

    const float* base = g_qkv + (size_t)b * NTOK * QKVW + h * HD;
    const float* qb = base;
    const float* kb = base + DIM_C;
    const float* vb = base + 2 * DIM_C;
    const float* bb = g_bias + (size_t)h * NN;

    // ---- load Q tile into A-fragment layout ----
#pragma unroll
    for (int l = 0; l < 8; l++) {
        int linear = tid + l * 128;              // 0..1023 float4s
        int row = linear >> 4;                   // 0..63
        int k4  = (linear & 15) * 4;
        int gr  = row0 + row;
        float4 v = make_float4(0.f, 0.f, 0.f, 0.f);
        if (gr < NTOK)
            v = *reinterpret_cast<const float4*>(qb + (size_t)gr * QKVW + k4);
        int mt = row >> 4, rr = row & 15;
        const float vv[4] = {v.x, v.y, v.z, v.w};
#pragma unroll
        for (int c = 0; c < 4; c++) {
            int k  = k4 + c;
            int ks = k >> 3, kc = k & 7;
            int ln = (rr & 7) * 4 + (kc & 3);
            int rg = (rr >> 3) + ((kc >> 2) << 1);
            Qf[(mt * 8 + ks) * 128 + ln * 4 + rg] = f2tf32(vv[c]);
        }
    }

    // per-thread softmax state: two rows (g, g+8) within warp's 16-row slab
    float m0 = -1e30f, m1 = -1e30f, l0 = 0.f, l1 = 0.f;
    float O[8][4];
#pragma unroll
    for (int nt = 0; nt < 8; nt++)
#pragma unroll
        for (int r = 0; r < 4; r++) O[nt][r] = 0.f;

    const int r_up = row0 + w * 16 + g;
    const int r_lo = r_up + 8;
    const float* b0p = bb + (size_t)(r_up < NTOK ? r_up : NTOK - 1) * NTOK;
    const float* b1p = bb + (size_t)(r_lo < NTOK ? r_lo : NTOK - 1) * NTOK;
    const float scale = 0.125f;

    for (int jt = 0; jt < 10; jt++) {
        const int col0 = jt * 64;
        __syncthreads();
        // ---- load K, V tiles into B-fragment layouts ----
#pragma unroll
        for (int l = 0; l < 8; l++) {
            int linear = tid + l * 128;
            int row = linear >> 4;               // token within tile
            int k4  = (linear & 15) * 4;
            int gc  = col0 + row;
            float4 kv = make_float4(0.f, 0.f, 0.f, 0.f);
            float4 vv = make_float4(0.f, 0.f, 0.f, 0.f);
            if (gc < NTOK) {
                kv = *reinterpret_cast<const float4*>(kb + (size_t)gc * QKVW + k4);
                vv = *reinterpret_cast<const float4*>(vb + (size_t)gc * QKVW + k4);
            }
            const float ka[4] = {kv.x, kv.y, kv.z, kv.w};
            const float va[4] = {vv.x, vv.y, vv.z, vv.w};
            int ntK = row >> 3, nnK = row & 7;     // K: token is n-dim
            int ksV = row >> 3, kmV = row & 7;     // V: token is k-dim
#pragma unroll
            for (int c = 0; c < 4; c++) {
                int k  = k4 + c;
                // K fragment: (k feature = k-dim, token = n-dim)
                int ks = k >> 3, kc = k & 7;
                Kf[(ks * 8 + ntK) * 64 + (nnK * 4 + (kc & 3)) * 2 + (kc >> 2)]
                    = f2tf32(ka[c]);
                // V fragment: (token = k-dim, d = n-dim)
                int nt = k >> 3, dn = k & 7;
                Vf[(ksV * 8 + nt) * 64 + (dn * 4 + (kmV & 3)) * 2 + (kmV >> 2)]
                    = f2tf32(va[c]);
            }
        }
        __syncthreads();

        // ---- S = Q K^T (warp: 16 x 64) ----
        float S[8][4];
#pragma unroll
        for (int nt = 0; nt < 8; nt++)
#pragma unroll
            for (int r = 0; r < 4; r++) S[nt][r] = 0.f;
#pragma unroll
        for (int ks = 0; ks < 8; ks++) {
            uint4 a = *reinterpret_cast<const uint4*>(&Qf[(w * 8 + ks) * 128 + lane * 4]);
#pragma unroll
            for (int nt = 0; nt < 8; nt++) {
                uint2 bfr = *reinterpret_cast<const uint2*>(&Kf[(ks * 8 + nt) * 64 + lane * 2]);
                mma_tf32(S[nt], a, bfr);
            }
        }

        // ---- scale + bias + mask ----
#pragma unroll
        for (int nt = 0; nt < 8; nt++) {
            int c = col0 + nt * 8 + t * 2;
            bool v0 = (c < NTOK), v1 = (c + 1 < NTOK);
            S[nt][0] = v0 ? S[nt][0] * scale + b0p[c]     : -1e30f;
            S[nt][1] = v1 ? S[nt][1] * scale + b0p[c + 1] : -1e30f;
            S[nt][2] = v0 ? S[nt][2] * scale + b1p[c]     : -1e30f;
            S[nt][3] = v1 ? S[nt][3] * scale + b1p[c + 1] : -1e30f;
        }

        // ---- online softmax (rows spread over 4 lanes: shfl_xor 1,2) ----
        float mx0 = -1e30f, mx1 = -1e30f;
#pragma unroll
        for (int nt = 0; nt < 8; nt++) {
            mx0 = fmaxf(mx0, fmaxf(S[nt][0], S[nt][1]));
            mx1 = fmaxf(mx1, fmaxf(S[nt][2], S[nt][3]));
        }
#pragma unroll
        for (int off = 1; off < 4; off <<= 1) {
            mx0 = fmaxf(mx0, __shfl_xor_sync(0xffffffffu, mx0, off));
            mx1 = fmaxf(mx1, __shfl_xor_sync(0xffffffffu, mx1, off));
        }
        float mn0 = fmaxf(m0, mx0), mn1 = fmaxf(m1, mx1);
        float a0 = __expf(m0 - mn0), a1 = __expf(m1 - mn1);
        float s0 = 0.f, s1 = 0.f;
#pragma unroll
        for (int nt = 0; nt < 8; nt++) {
            S[nt][0] = __expf(S[nt][0] - mn0);
            S[nt][1] = __expf(S[nt][1] - mn0);
            S[nt][2] = __expf(S[nt][2] - mn1);
            S[nt][3] = __expf(S[nt][3] - mn1);
            s0 += S[nt][0] + S[nt][1];
            s1 += S[nt][2] + S[nt][3];
        }
#pragma unroll
        for (int off = 1; off < 4; off <<= 1) {
            s0 += __shfl_xor_sync(0xffffffffu, s0, off);
            s1 += __shfl_xor_sync(0xffffffffu, s1, off);
        }
        l0 = l0 * a0 + s0;  m0 = mn0;
        l1 = l1 * a1 + s1;  m1 = mn1;
#pragma unroll
        for (int nt = 0; nt < 8; nt++) {
            O[nt][0] *= a0; O[nt][1] *= a0;
            O[nt][2] *= a1; O[nt][3] *= a1;
        }

        // ---- write P (D-frag) into warp-private A-frag smem ----
#pragma unroll
        for (int nt = 0; nt < 8; nt++) {
            int cc = nt * 8 + t * 2;          // ks == nt
            int kc0 = cc & 7, kc1 = (cc + 1) & 7;
            unsigned* pbase = &Pf[(w * 8 + nt) * 128];
            pbase[((g & 7) * 4 + (kc0 & 3)) * 4 + ((kc0 >> 2) << 1)]     = f2tf32(S[nt][0]);
            pbase[((g & 7) * 4 + (kc1 & 3)) * 4 + ((kc1 >> 2) << 1)]     = f2tf32(S[nt][1]);
            pbase[((g & 7) * 4 + (kc0 & 3)) * 4 + ((kc0 >> 2) << 1) + 1] = f2tf32(S[nt][2]);
            pbase[((g & 7) * 4 + (kc1 & 3)) * 4 + ((kc1 >> 2) << 1) + 1] = f2tf32(S[nt][3]);
        }
        __syncwarp();

        // ---- O += P @ V ----
#pragma unroll
        for (int ks = 0; ks < 8; ks++) {
            uint4 a = *reinterpret_cast<const uint4*>(&Pf[(w * 8 + ks) * 128 + lane * 4]);
#pragma unroll
            for (int nt = 0; nt < 8; nt++) {
                uint2 bfr = *reinterpret_cast<const uint2*>(&Vf[(ks * 8 + nt) * 64 + lane * 2]);
                mma_tf32(O[nt], a, bfr);
            }
        }
        __syncwarp();
    }

    // ---- epilogue ----
    float inv0 = 1.0f / l0, inv1 = 1.0f / l1;
#pragma unroll
    for (int nt = 0; nt < 8; nt++) {
        int c = nt * 8 + t * 2;
        if (r_up < NTOK) {
            float2 v = make_float2(O[nt][0] * inv0, O[nt][1] * inv0);
            *reinterpret_cast<float2*>(
                g_att + ((size_t)b * NTOK + r_up) * DIM_C + h * HD + c) = v;
        }
        if (r_lo < NTOK) {
            float2 v = make_float2(O[nt][2] * inv1, O[nt][3] * inv1);
            *reinterpret_cast<float2*>(
                g_att + ((size_t)b * NTOK + r_lo) * DIM_C + h * HD + c) = v;
        }
    }
}

// ---------------------------------------------------------------------------
// Launcher
// ---------------------------------------------------------------------------
extern "C" void kernel_launch(void* const* d_in, const int* in_sizes, int n_in,
                              void* d_out, int out_size) {
    const float* x      = (const float*)d_in[0];
    const float* qkv_w  = (const float*)d_in[1];
    const float* proj_w = (const float*)d_in[2];
    const float* proj_b = (const float*)d_in[3];
    const float* table  = (const float*)d_in[4];
    const int*   rel    = (const int*)d_in[5];
    float*       out    = (float*)d_out;

    void *qkv_p = nullptr, *att_p = nullptr;
    cudaGetSymbolAddress(&qkv_p, g_qkv);
    cudaGetSymbolAddress(&att_p, g_att);

    cudaFuncSetAttribute(attn_mma_kernel,
                         cudaFuncAttributeMaxDynamicSharedMemorySize,
                         ATTN_SMEM_BYTES);

    // 1) bias materialization
    bias_kernel<<<(NN + 255) / 256, 256>>>(table, rel);

    // 2) QKV projection: [18464,512] x [1536,512]^T
    gemm_tf32<false><<<dim3(QKVW / 128, (MROWS + 127) / 128), 256>>>(
        x, qkv_w, nullptr, (float*)qkv_p, MROWS, QKVW, DIM_C);

    // 3) attention
    attn_mma_kernel<<<dim3(10, HEADS, B_SZ), 128, ATTN_SMEM_BYTES>>>();

    // 4) output projection + bias -> d_out
    gemm_tf32<true><<<dim3(DIM_C / 128, (MROWS + 127) / 128), 256>>>(
        (const float*)att_p, proj_w, proj_b, out, MROWS, DIM_C, DIM_C);
}

// round 4
// speedup vs baseline: 2.9765x; 1.8755x over previous
#include <cuda_runtime.h>
#include <cstdint>
#include <cstddef>

// ---------------------------------------------------------------------------
// Problem constants
// ---------------------------------------------------------------------------
#define B_SZ   32
#define NTOK   577
#define HEADS  8
#define DIM_C  512
#define HD     64
#define MROWS  (B_SZ * NTOK)          // 18464
#define NN     (NTOK * NTOK)          // 332929
#define QKVW   (3 * DIM_C)            // 1536

// ---------------------------------------------------------------------------
// Scratch
// ---------------------------------------------------------------------------
__device__ float g_qkv[MROWS * QKVW];     // [B*N, 1536], tf32-rounded values
__device__ float g_bias[HEADS * NN];      // [H, N, N]
__device__ float g_att[MROWS * DIM_C];    // [B*N, 512], raw f32

// ---------------------------------------------------------------------------
// helpers
// ---------------------------------------------------------------------------
__device__ __forceinline__ unsigned f2tf32(float x) {
    unsigned r;
    asm("cvt.rna.tf32.f32 %0, %1;" : "=r"(r) : "f"(x));
    return r;
}

__device__ __forceinline__ void mma_tf32(float* d, const uint4& a, const uint2& b) {
    asm volatile(
        "mma.sync.aligned.m16n8k8.row.col.f32.tf32.tf32.f32 "
        "{%0,%1,%2,%3}, {%4,%5,%6,%7}, {%8,%9}, {%0,%1,%2,%3};\n"
        : "+f"(d[0]), "+f"(d[1]), "+f"(d[2]), "+f"(d[3])
        : "r"(a.x), "r"(a.y), "r"(a.z), "r"(a.w), "r"(b.x), "r"(b.y));
}

__device__ __forceinline__ void cp16(uint32_t dst, const void* src, bool valid) {
    int sz = valid ? 16 : 0;
    asm volatile("cp.async.cg.shared.global [%0], [%1], 16, %2;\n"
                 :: "r"(dst), "l"(src), "r"(sz));
}

#define CP_COMMIT() asm volatile("cp.async.commit_group;\n" ::: "memory")
#define CP_WAIT(n)  asm volatile("cp.async.wait_group %0;\n" :: "n"(n) : "memory")

// ---------------------------------------------------------------------------
// Kernel 0: materialize relative-position bias  bias[h][i][j]
// ---------------------------------------------------------------------------
__global__ void __launch_bounds__(256) bias_kernel(const float* __restrict__ table,
                                                   const int* __restrict__ rel) {
    int ij = blockIdx.x * 256 + threadIdx.x;
    if (ij >= NN) return;
    int idx = rel[ij];
    const float* t = table + (size_t)idx * HEADS;
#pragma unroll
    for (int h = 0; h < HEADS; h++)
        g_bias[(size_t)h * NN + ij] = t[h];
}

// ---------------------------------------------------------------------------
// cp.async-pipelined tf32 GEMM:  C[M,N] = A[M,K] @ B[N,K]^T (+ bias[N])
// 128x128 tile, BK=32, 3 smem stages (raw f32, XOR-swizzled), 256 thr = 8 warps.
// Fragment gather: conflict-free LDS.32 + cvt.rna in-register.
// ---------------------------------------------------------------------------
template<bool CVT_OUT, bool ADD_BIAS>
__global__ void __launch_bounds__(256, 2) gemm_cp(const float* __restrict__ A,
                                                  const float* __restrict__ Bm,
                                                  const float* __restrict__ bias,
                                                  float* __restrict__ C,
                                                  int M, int N, int K) {
    extern __shared__ float smf[];
    const uint32_t sbase = (uint32_t)__cvta_generic_to_shared(smf);

    const int tid  = threadIdx.x;
    const int lane = tid & 31;
    const int w    = tid >> 5;
    const int wm   = w >> 2, wn = w & 3;
    const int g    = lane >> 2, t = lane & 3;

    const int row0 = blockIdx.y * 128;
    const int col0 = blockIdx.x * 128;
    const int niter = K >> 5;

    float acc[4][4][4];
#pragma unroll
    for (int i = 0; i < 4; i++)
#pragma unroll
        for (int j = 0; j < 4; j++)
#pragma unroll
            for (int r = 0; r < 4; r++) acc[i][j][r] = 0.f;

    auto issue = [&](int it) {
        if (it < niter) {
            const int k0 = it << 5;
            const uint32_t ab = sbase + (uint32_t)(it % 3) * 32768u;
#pragma unroll
            for (int l = 0; l < 4; l++) {
                int c   = tid + (l << 8);
                int row = c >> 3;
                int k4  = (c & 7) << 2;
                uint32_t sw = (uint32_t)((row * 32 + (k4 ^ ((row & 7) << 2))) << 2);
                int ar = row0 + row;
                cp16(ab + sw, A + (size_t)(ar < M ? ar : M - 1) * K + k0 + k4, ar < M);
                cp16(ab + 16384u + sw, Bm + (size_t)(col0 + row) * K + k0 + k4, true);
            }
        }
        CP_COMMIT();
    };

    issue(0);
    issue(1);

    const int xm = g << 2;
    for (int it = 0; it < niter; it++) {
        CP_WAIT(1);
        __syncthreads();
        issue(it + 2);

        const float* As = smf + (it % 3) * 8192;
        const float* Bs = As + 4096;
#pragma unroll
        for (int ks = 0; ks < 4; ks++) {
            const int c0 = (ks * 8 + t) ^ xm;
            const int c1 = c0 ^ 4;
            uint4 a[4];
            uint2 b[4];
#pragma unroll
            for (int i = 0; i < 4; i++) {
                const float* p = As + (wm * 64 + i * 16 + g) * 32;
                a[i].x = f2tf32(p[c0]);
                a[i].y = f2tf32(p[256 + c0]);
                a[i].z = f2tf32(p[c1]);
                a[i].w = f2tf32(p[256 + c1]);
            }
#pragma unroll
            for (int j = 0; j < 4; j++) {
                const float* p = Bs + (wn * 32 + j * 8 + g) * 32;
                b[j].x = f2tf32(p[c0]);
                b[j].y = f2tf32(p[c1]);
            }
#pragma unroll
            for (int i = 0; i < 4; i++)
#pragma unroll
                for (int j = 0; j < 4; j++)
                    mma_tf32(acc[i][j], a[i], b[j]);
        }
    }

    // ---- epilogue ----
#pragma unroll
    for (int i = 0; i < 4; i++) {
        int r_up = row0 + wm * 64 + i * 16 + g;
        int r_lo = r_up + 8;
#pragma unroll
        for (int j = 0; j < 4; j++) {
            int c = col0 + wn * 32 + j * 8 + t * 2;
            float bx = 0.f, by = 0.f;
            if (ADD_BIAS) { bx = bias[c]; by = bias[c + 1]; }
            float v0 = acc[i][j][0] + bx, v1 = acc[i][j][1] + by;
            float v2 = acc[i][j][2] + bx, v3 = acc[i][j][3] + by;
            if (CVT_OUT) {
                v0 = __uint_as_float(f2tf32(v0));
                v1 = __uint_as_float(f2tf32(v1));
                v2 = __uint_as_float(f2tf32(v2));
                v3 = __uint_as_float(f2tf32(v3));
            }
            if (r_up < M)
                *reinterpret_cast<float2*>(C + (size_t)r_up * N + c) = make_float2(v0, v1);
            if (r_lo < M)
                *reinterpret_cast<float2*>(C + (size_t)r_lo * N + c) = make_float2(v2, v3);
        }
    }
}

// ---------------------------------------------------------------------------
// Flash attention, cp.async double-buffered K/V (raw f32 tiles, swizzled).
// Q prebuilt in A-frag order (tf32 bits, qkv is pre-rounded). grid (10,8,32),
// 128 thr = 4 warps, warp = 16 query rows.
// Smem words: Qf[4096] Pf[4096] | K0[4096] V0[4096] | K1[4096] V1[4096]
// ---------------------------------------------------------------------------
#define ATTN_SMEM_BYTES 98304

__global__ void __launch_bounds__(128) attn_cp_kernel() {
    extern __shared__ float smf[];
    const uint32_t sbase = (uint32_t)__cvta_generic_to_shared(smf);
    unsigned* Qf = reinterpret_cast<unsigned*>(smf);
    unsigned* Pf = Qf + 4096;

    const int tid  = threadIdx.x;
    const int lane = tid & 31;
    const int w    = tid >> 5;
    const int g    = lane >> 2;
    const int t    = lane & 3;

    const int b    = blockIdx.z;
    const int h    = blockIdx.y;
    const int row0 = blockIdx.x * 64;

    const float* base = g_qkv + (size_t)b * NTOK * QKVW + h * HD;
    const float* qb = base;
    const float* kb = base + DIM_C;
    const float* bb = g_bias + (size_t)h * NN;

    // ---- build Q tile in A-fragment order (bits only, already tf32) ----
#pragma unroll
    for (int l = 0; l < 8; l++) {
        int linear = tid + l * 128;
        int row = linear >> 4;
        int k4  = (linear & 15) * 4;
        int gr  = row0 + row;
        float4 v = make_float4(0.f, 0.f, 0.f, 0.f);
        if (gr < NTOK)
            v = *reinterpret_cast<const float4*>(qb + (size_t)gr * QKVW + k4);
        int mt = row >> 4, rr = row & 15;
        const float vv[4] = {v.x, v.y, v.z, v.w};
#pragma unroll
        for (int c = 0; c < 4; c++) {
            int k  = k4 + c;
            int ks = k >> 3, kc = k & 7;
            int ln = (rr & 7) * 4 + (kc & 3);
            int rg = (rr >> 3) + ((kc >> 2) << 1);
            Qf[(mt * 8 + ks) * 128 + ln * 4 + rg] = __float_as_uint(vv[c]);
        }
    }

    auto issueKV = [&](int jt) {
        if (jt < 10) {
            int c0 = jt * 64;
            uint32_t ab = sbase + 32768u + (uint32_t)(jt & 1) * 32768u;
#pragma unroll
            for (int l = 0; l < 8; l++) {
                int c   = tid + (l << 7);
                int row = c >> 4;
                int d4  = (c & 15) << 2;
                int gc  = c0 + row;
                bool v  = gc < NTOK;
                const float* srcK = kb + (size_t)(v ? gc : 0) * QKVW + d4;
                uint32_t swK = (uint32_t)((row * 64 + (d4 ^ ((row & 7) << 2))) << 2);
                uint32_t swV = (uint32_t)((row * 64 + (d4 ^ ((row & 3) << 3))) << 2);
                cp16(ab + swK, srcK, v);
                cp16(ab + 16384u + swV, srcK + DIM_C, v);
            }
        }
        CP_COMMIT();
    };

    issueKV(0);

    float m0 = -1e30f, m1 = -1e30f, l0 = 0.f, l1 = 0.f;
    float O[8][4];
#pragma unroll
    for (int nt = 0; nt < 8; nt++)
#pragma unroll
        for (int r = 0; r < 4; r++) O[nt][r] = 0.f;

    const int r_up = row0 + w * 16 + g;
    const int r_lo = r_up + 8;
    const float* b0p = bb + (size_t)(r_up < NTOK ? r_up : NTOK - 1) * NTOK;
    const float* b1p = bb + (size_t)(r_lo < NTOK ? r_lo : NTOK - 1) * NTOK;
    const float scale = 0.125f;
    const int xm = g << 2;

    for (int jt = 0; jt < 10; jt++) {
        const int col0 = jt * 64;
        CP_WAIT(0);
        __syncthreads();
        issueKV(jt + 1);

        const float* Ks = smf + 8192 + (jt & 1) * 8192;
        const float* Vs = Ks + 4096;

        // ---- S = Q K^T (warp: 16 x 64) ----
        float S[8][4];
#pragma unroll
        for (int nt = 0; nt < 8; nt++)
#pragma unroll
            for (int r = 0; r < 4; r++) S[nt][r] = 0.f;
#pragma unroll
        for (int ks = 0; ks < 8; ks++) {
            uint4 a = *reinterpret_cast<const uint4*>(&Qf[(w * 8 + ks) * 128 + lane * 4]);
            const int c0 = (ks * 8 + t) ^ xm;
            const int c1 = c0 ^ 4;
#pragma unroll
            for (int nt = 0; nt < 8; nt++) {
                const float* p = Ks + (nt * 8 + g) * 64;
                uint2 bf;
                bf.x = __float_as_uint(p[c0]);
                bf.y = __float_as_uint(p[c1]);
                mma_tf32(S[nt], a, bf);
            }
        }

        // ---- scale + bias + mask ----
#pragma unroll
        for (int nt = 0; nt < 8; nt++) {
            int c = col0 + nt * 8 + t * 2;
            bool v0 = (c < NTOK), v1 = (c + 1 < NTOK);
            S[nt][0] = v0 ? S[nt][0] * scale + b0p[c]     : -1e30f;
            S[nt][1] = v1 ? S[nt][1] * scale + b0p[c + 1] : -1e30f;
            S[nt][2] = v0 ? S[nt][2] * scale + b1p[c]     : -1e30f;
            S[nt][3] = v1 ? S[nt][3] * scale + b1p[c + 1] : -1e30f;
        }

        // ---- online softmax (rows spread over 4 lanes) ----
        float mx0 = -1e30f, mx1 = -1e30f;
#pragma unroll
        for (int nt = 0; nt < 8; nt++) {
            mx0 = fmaxf(mx0, fmaxf(S[nt][0], S[nt][1]));
            mx1 = fmaxf(mx1, fmaxf(S[nt][2], S[nt][3]));
        }
#pragma unroll
        for (int off = 1; off < 4; off <<= 1) {
            mx0 = fmaxf(mx0, __shfl_xor_sync(0xffffffffu, mx0, off));
            mx1 = fmaxf(mx1, __shfl_xor_sync(0xffffffffu, mx1, off));
        }
        float mn0 = fmaxf(m0, mx0), mn1 = fmaxf(m1, mx1);
        float a0 = __expf(m0 - mn0), a1 = __expf(m1 - mn1);
        float s0 = 0.f, s1 = 0.f;
#pragma unroll
        for (int nt = 0; nt < 8; nt++) {
            S[nt][0] = __expf(S[nt][0] - mn0);
            S[nt][1] = __expf(S[nt][1] - mn0);
            S[nt][2] = __expf(S[nt][2] - mn1);
            S[nt][3] = __expf(S[nt][3] - mn1);
            s0 += S[nt][0] + S[nt][1];
            s1 += S[nt][2] + S[nt][3];
        }
#pragma unroll
        for (int off = 1; off < 4; off <<= 1) {
            s0 += __shfl_xor_sync(0xffffffffu, s0, off);
            s1 += __shfl_xor_sync(0xffffffffu, s1, off);
        }
        l0 = l0 * a0 + s0;  m0 = mn0;
        l1 = l1 * a1 + s1;  m1 = mn1;
#pragma unroll
        for (int nt = 0; nt < 8; nt++) {
            O[nt][0] *= a0; O[nt][1] *= a0;
            O[nt][2] *= a1; O[nt][3] *= a1;
        }

        // ---- P (D-frag) -> warp-private A-frag smem ----
#pragma unroll
        for (int nt = 0; nt < 8; nt++) {
            int cc = nt * 8 + t * 2;
            int kc0 = cc & 7, kc1 = (cc + 1) & 7;
            unsigned* pbase = &Pf[(w * 8 + nt) * 128];
            pbase[((g & 7) * 4 + (kc0 & 3)) * 4 + ((kc0 >> 2) << 1)]     = f2tf32(S[nt][0]);
            pbase[((g & 7) * 4 + (kc1 & 3)) * 4 + ((kc1 >> 2) << 1)]     = f2tf32(S[nt][1]);
            pbase[((g & 7) * 4 + (kc0 & 3)) * 4 + ((kc0 >> 2) << 1) + 1] = f2tf32(S[nt][2]);
            pbase[((g & 7) * 4 + (kc1 & 3)) * 4 + ((kc1 >> 2) << 1) + 1] = f2tf32(S[nt][3]);
        }
        __syncwarp();

        // ---- O += P @ V ----
#pragma unroll
        for (int ks = 0; ks < 8; ks++) {
            uint4 a = *reinterpret_cast<const uint4*>(&Pf[(w * 8 + ks) * 128 + lane * 4]);
            const int swv = t << 3;
            const float* p0 = Vs + (ks * 8 + t) * 64;
            const float* p1 = p0 + 256;
#pragma unroll
            for (int nt = 0; nt < 8; nt++) {
                int d = nt * 8 + g;
                uint2 bf;
                bf.x = __float_as_uint(p0[d ^ swv]);
                bf.y = __float_as_uint(p1[d ^ swv]);
                mma_tf32(O[nt], a, bf);
            }
        }
        __syncwarp();
    }

    // ---- epilogue ----
    float inv0 = 1.0f / l0, inv1 = 1.0f / l1;
#pragma unroll
    for (int nt = 0; nt < 8; nt++) {
        int c = nt * 8 + t * 2;
        if (r_up < NTOK) {
            float2 v = make_float2(O[nt][0] * inv0, O[nt][1] * inv0);
            *reinterpret_cast<float2*>(
                g_att + ((size_t)b * NTOK + r_up) * DIM_C + h * HD + c) = v;
        }
        if (r_lo < NTOK) {
            float2 v = make_float2(O[nt][2] * inv1, O[nt][3] * inv1);
            *reinterpret_cast<float2*>(
                g_att + ((size_t)b * NTOK + r_lo) * DIM_C + h * HD + c) = v;
        }
    }
}

// ---------------------------------------------------------------------------
// Launcher
// ---------------------------------------------------------------------------
#define GEMM_SMEM_BYTES 98304

extern "C" void kernel_launch(void* const* d_in, const int* in_sizes, int n_in,
                              void* d_out, int out_size) {
    const float* x      = (const float*)d_in[0];
    const float* qkv_w  = (const float*)d_in[1];
    const float* proj_w = (const float*)d_in[2];
    const float* proj_b = (const float*)d_in[3];
    const float* table  = (const float*)d_in[4];
    const int*   rel    = (const int*)d_in[5];
    float*       out    = (float*)d_out;

    void *qkv_p = nullptr, *att_p = nullptr;
    cudaGetSymbolAddress(&qkv_p, g_qkv);
    cudaGetSymbolAddress(&att_p, g_att);

    cudaFuncSetAttribute(gemm_cp<true, false>,
                         cudaFuncAttributeMaxDynamicSharedMemorySize, GEMM_SMEM_BYTES);
    cudaFuncSetAttribute(gemm_cp<false, true>,
                         cudaFuncAttributeMaxDynamicSharedMemorySize, GEMM_SMEM_BYTES);
    cudaFuncSetAttribute(attn_cp_kernel,
                         cudaFuncAttributeMaxDynamicSharedMemorySize, ATTN_SMEM_BYTES);

    // 1) bias materialization
    bias_kernel<<<(NN + 255) / 256, 256>>>(table, rel);

    // 2) QKV projection (outputs tf32-rounded values)
    gemm_cp<true, false><<<dim3(QKVW / 128, (MROWS + 127) / 128), 256, GEMM_SMEM_BYTES>>>(
        x, qkv_w, nullptr, (float*)qkv_p, MROWS, QKVW, DIM_C);

    // 3) attention
    attn_cp_kernel<<<dim3(10, HEADS, B_SZ), 128, ATTN_SMEM_BYTES>>>();

    // 4) output projection + bias -> d_out (full f32 out)
    gemm_cp<false, true><<<dim3(DIM_C / 128, (MROWS + 127) / 128), 256, GEMM_SMEM_BYTES>>>(
        (const float*)att_p, proj_w, proj_b, out, MROWS, DIM_C, DIM_C);
}

// round 7
// speedup vs baseline: 3.1177x; 1.0474x over previous
#include <cuda_runtime.h>
#include <cstdint>
#include <cstddef>

// ---------------------------------------------------------------------------
// Problem constants
// ---------------------------------------------------------------------------
#define B_SZ   32
#define NTOK   577
#define HEADS  8
#define DIM_C  512
#define HD     64
#define MROWS  (B_SZ * NTOK)          // 18464
#define NN     (NTOK * NTOK)          // 332929
#define QKVW   (3 * DIM_C)            // 1536

// ---------------------------------------------------------------------------
// Scratch
// ---------------------------------------------------------------------------
__device__ float g_qkv[MROWS * QKVW];     // [B*N, 1536], tf32-rounded
__device__ float g_bias[HEADS * NN];      // [H, N, N]
__device__ float g_att[MROWS * DIM_C];    // [B*N, 512], tf32-rounded
__device__ float g_xr[MROWS * DIM_C];     // x, tf32-rounded
__device__ float g_wqkv[QKVW * DIM_C];    // qkv_w, tf32-rounded
__device__ float g_wp[DIM_C * DIM_C];     // proj_w, tf32-rounded

// ---------------------------------------------------------------------------
// helpers
// ---------------------------------------------------------------------------
__device__ __forceinline__ unsigned f2tf32(float x) {
    unsigned r;
    asm("cvt.rna.tf32.f32 %0, %1;" : "=r"(r) : "f"(x));
    return r;
}

__device__ __forceinline__ void mma_tf32(float* d, const uint4& a, const uint2& b) {
    asm volatile(
        "mma.sync.aligned.m16n8k8.row.col.f32.tf32.tf32.f32 "
        "{%0,%1,%2,%3}, {%4,%5,%6,%7}, {%8,%9}, {%0,%1,%2,%3};\n"
        : "+f"(d[0]), "+f"(d[1]), "+f"(d[2]), "+f"(d[3])
        : "r"(a.x), "r"(a.y), "r"(a.z), "r"(a.w), "r"(b.x), "r"(b.y));
}

__device__ __forceinline__ void ldsm4(uint4& r, uint32_t addr) {
    asm volatile("ldmatrix.sync.aligned.m8n8.x4.shared.b16 {%0,%1,%2,%3}, [%4];"
                 : "=r"(r.x), "=r"(r.y), "=r"(r.z), "=r"(r.w) : "r"(addr));
}

__device__ __forceinline__ void cp16(uint32_t dst, const void* src, bool valid) {
    int sz = valid ? 16 : 0;
    asm volatile("cp.async.cg.shared.global [%0], [%1], 16, %2;\n"
                 :: "r"(dst), "l"(src), "r"(sz));
}

#define CP_COMMIT() asm volatile("cp.async.commit_group;\n" ::: "memory")
#define CP_WAIT(n)  asm volatile("cp.async.wait_group %0;\n" :: "n"(n) : "memory")

// ---------------------------------------------------------------------------
// Kernel: round fp32 -> tf32 values (vectorized)
// ---------------------------------------------------------------------------
__global__ void __launch_bounds__(256) round_kernel(const float* __restrict__ src,
                                                    float* __restrict__ dst, int n4) {
    int i = blockIdx.x * 256 + threadIdx.x;
    if (i >= n4) return;
    float4 v = reinterpret_cast<const float4*>(src)[i];
    v.x = __uint_as_float(f2tf32(v.x));
    v.y = __uint_as_float(f2tf32(v.y));
    v.z = __uint_as_float(f2tf32(v.z));
    v.w = __uint_as_float(f2tf32(v.w));
    reinterpret_cast<float4*>(dst)[i] = v;
}

// ---------------------------------------------------------------------------
// Kernel: materialize relative-position bias  bias[h][i][j]
// ---------------------------------------------------------------------------
__global__ void __launch_bounds__(256) bias_kernel(const float* __restrict__ table,
                                                   const int* __restrict__ rel) {
    int ij = blockIdx.x * 256 + threadIdx.x;
    if (ij >= NN) return;
    int idx = rel[ij];
    const float* t = table + (size_t)idx * HEADS;
#pragma unroll
    for (int h = 0; h < HEADS; h++)
        g_bias[(size_t)h * NN + ij] = t[h];
}

// ---------------------------------------------------------------------------
// cp.async + ldmatrix tf32 GEMM:  C[M,N] = A[M,K] @ B[N,K]^T (+ bias[N])
// Inputs pre-rounded to tf32 values. 128x128 tile, BK=32, 3 stages,
// 256 thr = 8 warps (2M x 4N). Per ks: 4 LDSM.x4 (A) + 2 LDSM.x4 (B) + 16 MMA.
// ---------------------------------------------------------------------------
template<bool CVT_OUT, bool ADD_BIAS>
__global__ void __launch_bounds__(256, 2) gemm_cp(const float* __restrict__ A,
                                                  const float* __restrict__ Bm,
                                                  const float* __restrict__ bias,
                                                  float* __restrict__ C,
                                                  int M, int N, int K) {
    extern __shared__ float smf[];
    const uint32_t sbase = (uint32_t)__cvta_generic_to_shared(smf);

    const int tid  = threadIdx.x;
    const int lane = tid & 31;
    const int w    = tid >> 5;
    const int wm   = w >> 2, wn = w & 3;
    const int g    = lane >> 2, t = lane & 3;

    const int row0 = blockIdx.y * 128;
    const int col0 = blockIdx.x * 128;
    const int niter = K >> 5;

    float acc[4][4][4];
#pragma unroll
    for (int i = 0; i < 4; i++)
#pragma unroll
        for (int j = 0; j < 4; j++)
#pragma unroll
            for (int r = 0; r < 4; r++) acc[i][j][r] = 0.f;

    auto issue = [&](int it) {
        if (it < niter) {
            const int k0 = it << 5;
            const uint32_t ab = sbase + (uint32_t)(it % 3) * 32768u;
#pragma unroll
            for (int l = 0; l < 4; l++) {
                int c   = tid + (l << 8);
                int row = c >> 3;
                int k4  = (c & 7) << 2;
                uint32_t sw = (uint32_t)((row * 32 + (k4 ^ ((row & 7) << 2))) << 2);
                int ar = row0 + row;
                cp16(ab + sw, A + (size_t)(ar < M ? ar : M - 1) * K + k0 + k4, ar < M);
                cp16(ab + 16384u + sw, Bm + (size_t)(col0 + row) * K + k0 + k4, true);
            }
        }
        CP_COMMIT();
    };

    issue(0);
    issue(1);

    // ldmatrix base offsets (bytes, relative to stage base)
    uint32_t baseA[4], baseB[2];
#pragma unroll
    for (int i = 0; i < 4; i++) {
        int row = wm * 64 + i * 16 + (lane & 15);
        int kg  = lane >> 4;
        baseA[i] = (uint32_t)((row * 32 + ((kg * 4) ^ ((row & 7) << 2))) << 2);
    }
#pragma unroll
    for (int u = 0; u < 2; u++) {
        int n  = wn * 32 + u * 16 + ((lane >> 4) << 3) + (lane & 7);
        int kg = (lane >> 3) & 1;
        baseB[u] = 16384u + (uint32_t)((n * 32 + ((kg * 4) ^ ((n & 7) << 2))) << 2);
    }

    for (int it = 0; it < niter; it++) {
        CP_WAIT(1);
        __syncthreads();
        issue(it + 2);

        const uint32_t stage = sbase + (uint32_t)(it % 3) * 32768u;
#pragma unroll
        for (int ks = 0; ks < 4; ks++) {
            const uint32_t kx = (uint32_t)(ks << 5);
            uint4 a[4], bb2[2];
#pragma unroll
            for (int i = 0; i < 4; i++) ldsm4(a[i], stage + (baseA[i] ^ kx));
#pragma unroll
            for (int u = 0; u < 2; u++) ldsm4(bb2[u], stage + (baseB[u] ^ kx));
            uint2 b[4];
            b[0] = make_uint2(bb2[0].x, bb2[0].y);
            b[1] = make_uint2(bb2[0].z, bb2[0].w);
            b[2] = make_uint2(bb2[1].x, bb2[1].y);
            b[3] = make_uint2(bb2[1].z, bb2[1].w);
#pragma unroll
            for (int i = 0; i < 4; i++)
#pragma unroll
                for (int j = 0; j < 4; j++)
                    mma_tf32(acc[i][j], a[i], b[j]);
        }
    }

    // ---- epilogue ----
#pragma unroll
    for (int i = 0; i < 4; i++) {
        int r_up = row0 + wm * 64 + i * 16 + g;
        int r_lo = r_up + 8;
#pragma unroll
        for (int j = 0; j < 4; j++) {
            int c = col0 + wn * 32 + j * 8 + t * 2;
            float bx = 0.f, by = 0.f;
            if (ADD_BIAS) { bx = bias[c]; by = bias[c + 1]; }
            float v0 = acc[i][j][0] + bx, v1 = acc[i][j][1] + by;
            float v2 = acc[i][j][2] + bx, v3 = acc[i][j][3] + by;
            if (CVT_OUT) {
                v0 = __uint_as_float(f2tf32(v0));
                v1 = __uint_as_float(f2tf32(v1));
                v2 = __uint_as_float(f2tf32(v2));
                v3 = __uint_as_float(f2tf32(v3));
            }
            if (r_up < M)
                *reinterpret_cast<float2*>(C + (size_t)r_up * N + c) = make_float2(v0, v1);
            if (r_lo < M)
                *reinterpret_cast<float2*>(C + (size_t)r_lo * N + c) = make_float2(v2, v3);
        }
    }
}

// ---------------------------------------------------------------------------
// Flash attention. 256 thr = 8 warps, 128 query rows/CTA, grid (5, 8, 32).
// Q raw-swizzled via cp.async, fragments via ldmatrix. K double-buffered.
// Smem words: Qs[8192] Pf[8192] | stage0: K[4096] V[4096] | stage1: K V
// ---------------------------------------------------------------------------
#define ATTN_SMEM_BYTES 131072

__global__ void __launch_bounds__(256) attn_cp_kernel() {
    extern __shared__ float smf[];
    const uint32_t sbase = (uint32_t)__cvta_generic_to_shared(smf);
    unsigned* Pf = reinterpret_cast<unsigned*>(smf) + 8192;

    const int tid  = threadIdx.x;
    const int lane = tid & 31;
    const int w    = tid >> 5;
    const int g    = lane >> 2;
    const int t    = lane & 3;

    const int b    = blockIdx.z;
    const int h    = blockIdx.y;
    const int row0 = blockIdx.x * 128;

    const float* base = g_qkv + (size_t)b * NTOK * QKVW + h * HD;
    const float* qb = base;
    const float* kb = base + DIM_C;
    const float* bb = g_bias + (size_t)h * NN;

    // ---- Q tile via cp.async (raw swizzled: off = row*64 + (d4 ^ ((row&7)<<2))) ----
#pragma unroll
    for (int l = 0; l < 8; l++) {
        int c   = tid + (l << 8);
        int row = c >> 4;                 // 0..127
        int d4  = (c & 15) << 2;
        int gr  = row0 + row;
        uint32_t sw = (uint32_t)((row * 64 + (d4 ^ ((row & 7) << 2))) << 2);
        cp16(sbase + sw, qb + (size_t)(gr < NTOK ? gr : 0) * QKVW + d4, gr < NTOK);
    }

    auto issueKV = [&](int jt) {
        if (jt < 10) {
            int c0 = jt * 64;
            uint32_t ab = sbase + 65536u + (uint32_t)(jt & 1) * 32768u;
#pragma unroll
            for (int l = 0; l < 4; l++) {
                int c   = tid + (l << 8);
                int row = c >> 4;         // token 0..63
                int d4  = (c & 15) << 2;
                int gc  = c0 + row;
                bool v  = gc < NTOK;
                const float* srcK = kb + (size_t)(v ? gc : 0) * QKVW + d4;
                uint32_t swK = (uint32_t)((row * 64 + (d4 ^ ((row & 7) << 2))) << 2);
                uint32_t swV = (uint32_t)((row * 64 + (d4 ^ ((row & 3) << 3))) << 2);
                cp16(ab + swK, srcK, v);
                cp16(ab + 16384u + swV, srcK + DIM_C, v);
            }
        }
        CP_COMMIT();
    };

    issueKV(0);   // group contains Q + first KV stage

    // ldmatrix base offsets
    uint32_t baseQ, baseK[4];
    {
        int row = w * 16 + (lane & 15);
        int kg  = lane >> 4;
        baseQ = (uint32_t)((row * 64 + ((kg * 4) ^ ((row & 7) << 2))) << 2);
    }
#pragma unroll
    for (int j = 0; j < 4; j++) {
        int n  = j * 16 + ((lane >> 4) << 3) + (lane & 7);
        int kg = (lane >> 3) & 1;
        baseK[j] = (uint32_t)((n * 64 + ((kg * 4) ^ ((n & 7) << 2))) << 2);
    }

    float m0 = -1e30f, m1 = -1e30f, l0 = 0.f, l1 = 0.f;
    float O[8][4];
#pragma unroll
    for (int nt = 0; nt < 8; nt++)
#pragma unroll
        for (int r = 0; r < 4; r++) O[nt][r] = 0.f;

    const int r_up = row0 + w * 16 + g;
    const int r_lo = r_up + 8;
    const float* b0p = bb + (size_t)(r_up < NTOK ? r_up : NTOK - 1) * NTOK;
    const float* b1p = bb + (size_t)(r_lo < NTOK ? r_lo : NTOK - 1) * NTOK;
    const float scale = 0.125f;

    for (int jt = 0; jt < 10; jt++) {
        const int col0 = jt * 64;
        CP_WAIT(0);
        __syncthreads();
        issueKV(jt + 1);

        const uint32_t kvb = sbase + 65536u + (uint32_t)(jt & 1) * 32768u;
        const float* Vs = smf + 16384 + (jt & 1) * 8192 + 4096;

        // ---- S = Q K^T (warp: 16 x 64) ----
        float S[8][4];
#pragma unroll
        for (int nt = 0; nt < 8; nt++)
#pragma unroll
            for (int r = 0; r < 4; r++) S[nt][r] = 0.f;
#pragma unroll
        for (int ks = 0; ks < 8; ks++) {
            const uint32_t kx = (uint32_t)(ks << 5);
            uint4 aq;
            ldsm4(aq, sbase + (baseQ ^ kx));
#pragma unroll
            for (int j = 0; j < 4; j++) {
                uint4 kf;
                ldsm4(kf, kvb + (baseK[j] ^ kx));
                mma_tf32(S[2 * j],     aq, make_uint2(kf.x, kf.y));
                mma_tf32(S[2 * j + 1], aq, make_uint2(kf.z, kf.w));
            }
        }

        // ---- scale + bias + mask ----
#pragma unroll
        for (int nt = 0; nt < 8; nt++) {
            int c = col0 + nt * 8 + t * 2;
            bool v0 = (c < NTOK), v1 = (c + 1 < NTOK);
            S[nt][0] = v0 ? S[nt][0] * scale + b0p[c]     : -1e30f;
            S[nt][1] = v1 ? S[nt][1] * scale + b0p[c + 1] : -1e30f;
            S[nt][2] = v0 ? S[nt][2] * scale + b1p[c]     : -1e30f;
            S[nt][3] = v1 ? S[nt][3] * scale + b1p[c + 1] : -1e30f;
        }

        // ---- online softmax (rows spread over 4 lanes) ----
        float mx0 = -1e30f, mx1 = -1e30f;
#pragma unroll
        for (int nt = 0; nt < 8; nt++) {
            mx0 = fmaxf(mx0, fmaxf(S[nt][0], S[nt][1]));
            mx1 = fmaxf(mx1, fmaxf(S[nt][2], S[nt][3]));
        }
#pragma unroll
        for (int off = 1; off < 4; off <<= 1) {
            mx0 = fmaxf(mx0, __shfl_xor_sync(0xffffffffu, mx0, off));
            mx1 = fmaxf(mx1, __shfl_xor_sync(0xffffffffu, mx1, off));
        }
        float mn0 = fmaxf(m0, mx0), mn1 = fmaxf(m1, mx1);
        float a0 = __expf(m0 - mn0), a1 = __expf(m1 - mn1);
        float s0 = 0.f, s1 = 0.f;
#pragma unroll
        for (int nt = 0; nt < 8; nt++) {
            S[nt][0] = __expf(S[nt][0] - mn0);
            S[nt][1] = __expf(S[nt][1] - mn0);
            S[nt][2] = __expf(S[nt][2] - mn1);
            S[nt][3] = __expf(S[nt][3] - mn1);
            s0 += S[nt][0] + S[nt][1];
            s1 += S[nt][2] + S[nt][3];
        }
#pragma unroll
        for (int off = 1; off < 4; off <<= 1) {
            s0 += __shfl_xor_sync(0xffffffffu, s0, off);
            s1 += __shfl_xor_sync(0xffffffffu, s1, off);
        }
        l0 = l0 * a0 + s0;  m0 = mn0;
        l1 = l1 * a1 + s1;  m1 = mn1;
#pragma unroll
        for (int nt = 0; nt < 8; nt++) {
            O[nt][0] *= a0; O[nt][1] *= a0;
            O[nt][2] *= a1; O[nt][3] *= a1;
        }

        // ---- P (D-frag) -> warp-private A-frag smem ----
#pragma unroll
        for (int nt = 0; nt < 8; nt++) {
            int cc = nt * 8 + t * 2;
            int kc0 = cc & 7, kc1 = (cc + 1) & 7;
            unsigned* pbase = &Pf[(w * 8 + nt) * 128];
            pbase[((g & 7) * 4 + (kc0 & 3)) * 4 + ((kc0 >> 2) << 1)]     = f2tf32(S[nt][0]);
            pbase[((g & 7) * 4 + (kc1 & 3)) * 4 + ((kc1 >> 2) << 1)]     = f2tf32(S[nt][1]);
            pbase[((g & 7) * 4 + (kc0 & 3)) * 4 + ((kc0 >> 2) << 1) + 1] = f2tf32(S[nt][2]);
            pbase[((g & 7) * 4 + (kc1 & 3)) * 4 + ((kc1 >> 2) << 1) + 1] = f2tf32(S[nt][3]);
        }
        __syncwarp();

        // ---- O += P @ V ----
#pragma unroll
        for (int ks = 0; ks < 8; ks++) {
            uint4 a = *reinterpret_cast<const uint4*>(&Pf[(w * 8 + ks) * 128 + lane * 4]);
            const int swv = t << 3;
            const float* p0 = Vs + (ks * 8 + t) * 64;
            const float* p1 = p0 + 256;
#pragma unroll
            for (int nt = 0; nt < 8; nt++) {
                int d = nt * 8 + g;
                uint2 bf;
                bf.x = __float_as_uint(p0[d ^ swv]);
                bf.y = __float_as_uint(p1[d ^ swv]);
                mma_tf32(O[nt], a, bf);
            }
        }
        __syncwarp();
    }

    // ---- epilogue (write tf32-rounded so out-proj needs no cvt) ----
    float inv0 = 1.0f / l0, inv1 = 1.0f / l1;
#pragma unroll
    for (int nt = 0; nt < 8; nt++) {
        int c = nt * 8 + t * 2;
        if (r_up < NTOK) {
            float2 v;
            v.x = __uint_as_float(f2tf32(O[nt][0] * inv0));
            v.y = __uint_as_float(f2tf32(O[nt][1] * inv0));
            *reinterpret_cast<float2*>(
                g_att + ((size_t)b * NTOK + r_up) * DIM_C + h * HD + c) = v;
        }
        if (r_lo < NTOK) {
            float2 v;
            v.x = __uint_as_float(f2tf32(O[nt][2] * inv1));
            v.y = __uint_as_float(f2tf32(O[nt][3] * inv1));
            *reinterpret_cast<float2*>(
                g_att + ((size_t)b * NTOK + r_lo) * DIM_C + h * HD + c) = v;
        }
    }
}

// ---------------------------------------------------------------------------
// Launcher
// ---------------------------------------------------------------------------
#define GEMM_SMEM_BYTES 98304

extern "C" void kernel_launch(void* const* d_in, const int* in_sizes, int n_in,
                              void* d_out, int out_size) {
    const float* x      = (const float*)d_in[0];
    const float* qkv_w  = (const float*)d_in[1];
    const float* proj_w = (const float*)d_in[2];
    const float* proj_b = (const float*)d_in[3];
    const float* table  = (const float*)d_in[4];
    const int*   rel    = (const int*)d_in[5];
    float*       out    = (float*)d_out;

    void *qkv_p = nullptr, *att_p = nullptr, *xr_p = nullptr, *wq_p = nullptr, *wp_p = nullptr;
    cudaGetSymbolAddress(&qkv_p, g_qkv);
    cudaGetSymbolAddress(&att_p, g_att);
    cudaGetSymbolAddress(&xr_p,  g_xr);
    cudaGetSymbolAddress(&wq_p,  g_wqkv);
    cudaGetSymbolAddress(&wp_p,  g_wp);

    cudaFuncSetAttribute(gemm_cp<true, false>,
                         cudaFuncAttributeMaxDynamicSharedMemorySize, GEMM_SMEM_BYTES);
    cudaFuncSetAttribute(gemm_cp<false, true>,
                         cudaFuncAttributeMaxDynamicSharedMemorySize, GEMM_SMEM_BYTES);
    cudaFuncSetAttribute(attn_cp_kernel,
                         cudaFuncAttributeMaxDynamicSharedMemorySize, ATTN_SMEM_BYTES);

    // 0) pre-round inputs to tf32 values
    round_kernel<<<(MROWS * DIM_C / 4 + 255) / 256, 256>>>(x, (float*)xr_p, MROWS * DIM_C / 4);
    round_kernel<<<(QKVW * DIM_C / 4 + 255) / 256, 256>>>(qkv_w, (float*)wq_p, QKVW * DIM_C / 4);
    round_kernel<<<(DIM_C * DIM_C / 4 + 255) / 256, 256>>>(proj_w, (float*)wp_p, DIM_C * DIM_C / 4);

    // 1) bias materialization
    bias_kernel<<<(NN + 255) / 256, 256>>>(table, rel);

    // 2) QKV projection (rounds outputs)
    gemm_cp<true, false><<<dim3(QKVW / 128, (MROWS + 127) / 128), 256, GEMM_SMEM_BYTES>>>(
        (const float*)xr_p, (const float*)wq_p, nullptr, (float*)qkv_p, MROWS, QKVW, DIM_C);

    // 3) attention (writes rounded g_att)
    attn_cp_kernel<<<dim3(5, HEADS, B_SZ), 256, ATTN_SMEM_BYTES>>>();

    // 4) output projection + bias -> d_out (full f32 out)
    gemm_cp<false, true><<<dim3(DIM_C / 128, (MROWS + 127) / 128), 256, GEMM_SMEM_BYTES>>>(
        (const float*)att_p, (const float*)wp_p, proj_b, out, MROWS, DIM_C, DIM_C);
}